// round 12
// baseline (speedup 1.0000x reference)
#include <cuda_runtime.h>

// Problem constants (fixed by the reference)
#define T_TOTAL   262144
#define S_DIM     512
#define K_ROWS    258       // NUM_KNOTS + DEGREE - 1
#define NKNOTS    262       // NUM_KNOTS + 2*DEGREE
#define DEG       3

#define TIMES_PER_BLOCK 128
#define NBLOCKS (T_TOTAL / TIMES_PER_BLOCK)   // 2048

// Scratch for weight row sums (allocation-free per harness rules)
__device__ float g_rowsum[K_ROWS];

// ---------------------------------------------------------------------------
// Kernel 1: rowsum[r] = sum_s W[r, s]   (258 x 512, negligible cost)
// ---------------------------------------------------------------------------
__global__ void rowsum_kernel(const float* __restrict__ weights) {
    const int row = blockIdx.x;
    float s = 0.0f;
    for (int c = threadIdx.x; c < S_DIM; c += blockDim.x)
        s += weights[row * S_DIM + c];
    #pragma unroll
    for (int o = 16; o > 0; o >>= 1)
        s += __shfl_down_sync(0xffffffffu, s, o);
    __shared__ float ws[4];
    const int w = threadIdx.x >> 5;
    if ((threadIdx.x & 31) == 0) ws[w] = s;
    __syncthreads();
    if (threadIdx.x == 0)
        g_rowsum[row] = ws[0] + ws[1] + ws[2] + ws[3];
}

// ---------------------------------------------------------------------------
// Kernel 2: 512 threads/block, 128 times/block.
//   Phase A: stage knots in smem.
//   Phase B: threads 0..127 do independent span search + de Boor, write
//            coeffs (float4) + base to smem, per-time sum to gmem.
//   Phase C: 32 streaming iterations; weight rows register-cached and
//            reloaded only on (warp-uniform, rare) span-base change.
// NOTE: no min-blocks clamp — R10 showed that squeezing to 32 regs spills
// the weight cache to local memory (L1 84.6%, DRAM 55%) and regresses.
// ---------------------------------------------------------------------------
__global__ __launch_bounds__(512)
void bspline_kernel(const float* __restrict__ times,
                    const float* __restrict__ weights,
                    const float* __restrict__ knots,
                    float* __restrict__ out)
{
    __shared__ float  s_knots[NKNOTS];
    __shared__ float4 s_c[TIMES_PER_BLOCK];
    __shared__ int    s_base[TIMES_PER_BLOCK];

    const int tid = threadIdx.x;
    const int t0  = blockIdx.x * TIMES_PER_BLOCK;

    // Phase A: knots -> smem
    if (tid < NKNOTS) s_knots[tid] = knots[tid];
    __syncthreads();

    // Phase B: 128 parallel coefficient computations
    if (tid < TIMES_PER_BLOCK) {
        const float t = times[t0 + tid];
        float c0 = 0.f, c1 = 0.f, c2 = 0.f, c3 = 0.f, sum = 0.f;
        int base = 0;

        // Valid half-open span exists only if t < knots[258] (= t_max).
        // t == t_max => reference basis row is all zeros.
        if (t < s_knots[NKNOTS - DEG - 1]) {
            // binary search: largest i in [3, 257] with knots[i] <= t
            int lo = DEG, hi = NKNOTS - DEG - 2;   // 3 .. 257
            while (lo < hi) {
                const int mid = (lo + hi + 1) >> 1;
                if (s_knots[mid] <= t) lo = mid; else hi = mid - 1;
            }
            const int i = lo;  // knots[i] <= t < knots[i+1], non-empty span

            // Local de Boor triangle (all denominators > 0 in a valid span;
            // algebraically identical to the reference's recursion).
            float Nv[DEG + 1], left[DEG + 1], right[DEG + 1];
            Nv[0] = 1.0f;
            #pragma unroll
            for (int j = 1; j <= DEG; j++) {
                left[j]  = t - s_knots[i + 1 - j];
                right[j] = s_knots[i + j] - t;
                float saved = 0.0f;
                #pragma unroll
                for (int r = 0; r < j; r++) {
                    const float temp = Nv[r] / (right[r + 1] + left[j - r]);
                    Nv[r] = saved + right[r + 1] * temp;
                    saved = left[j - r] * temp;
                }
                Nv[j] = saved;
            }
            base = i - DEG;
            c0 = Nv[0]; c1 = Nv[1]; c2 = Nv[2]; c3 = Nv[3];
            sum = c0 * g_rowsum[base]     + c1 * g_rowsum[base + 1]
                + c2 * g_rowsum[base + 2] + c3 * g_rowsum[base + 3];
        }

        s_c[tid]    = make_float4(c0, c1, c2, c3);
        s_base[tid] = base;
        // b_splines_sum lives after the T*S b_splines block
        out[(size_t)T_TOTAL * S_DIM + (t0 + tid)] = sum;
    }
    __syncthreads();

    // Phase C: streaming combine + store with register-cached weight rows
    const int tl   = tid >> 7;    // 0..3: time sub-slot (warp-uniform)
    const int lane = tid & 127;   // column group
    const int col  = lane << 2;   // 4 columns per thread

    // Prime the weight-row register cache with the first slot's base
    int curBase = s_base[tl];
    {
        const float* wp0 = weights + (size_t)curBase * S_DIM + col;
        // (initial load done below via the same reload vars)
    }
    const float* wp = weights + (size_t)curBase * S_DIM + col;
    float4 w0 = __ldg((const float4*)(wp));
    float4 w1 = __ldg((const float4*)(wp + S_DIM));
    float4 w2 = __ldg((const float4*)(wp + 2 * S_DIM));
    float4 w3 = __ldg((const float4*)(wp + 3 * S_DIM));

    // Incremental pointers (fewer IMADs in the hot loop)
    float* out_ptr = out + (size_t)(t0 + tl) * S_DIM + col;
    const float4* c_ptr    = &s_c[tl];
    const int*    base_ptr = &s_base[tl];

    #pragma unroll 4
    for (int it = 0; it < TIMES_PER_BLOCK / 4; ++it) {
        const int base = *base_ptr;
        if (base != curBase) {                     // warp-uniform, rare
            curBase = base;
            const float* wq = weights + (size_t)base * S_DIM + col;
            w0 = __ldg((const float4*)(wq));
            w1 = __ldg((const float4*)(wq + S_DIM));
            w2 = __ldg((const float4*)(wq + 2 * S_DIM));
            w3 = __ldg((const float4*)(wq + 3 * S_DIM));
        }
        const float4 c = *c_ptr;                   // LDS.128 broadcast

        float4 o;
        o.x = c.x * w0.x + c.y * w1.x + c.z * w2.x + c.w * w3.x;
        o.y = c.x * w0.y + c.y * w1.y + c.z * w2.y + c.w * w3.y;
        o.z = c.x * w0.z + c.y * w1.z + c.z * w2.z + c.w * w3.z;
        o.w = c.x * w0.w + c.y * w1.w + c.z * w2.w + c.w * w3.w;

        // Streaming store: 512 MB with zero reuse — don't pollute L2.
        __stcs((float4*)out_ptr, o);

        out_ptr  += 4 * S_DIM;
        c_ptr    += 4;
        base_ptr += 4;
    }
}

// ---------------------------------------------------------------------------
// Launch: inputs are (times, weights, knots) per metadata order.
// Output buffer: [ b_splines (T*S floats) | b_splines_sum (T floats) ].
// ---------------------------------------------------------------------------
extern "C" void kernel_launch(void* const* d_in, const int* in_sizes, int n_in,
                              void* d_out, int out_size) {
    const float* times   = (const float*)d_in[0];
    const float* weights = (const float*)d_in[1];
    const float* knots   = (const float*)d_in[2];
    float* out = (float*)d_out;

    rowsum_kernel<<<K_ROWS, 128>>>(weights);
    bspline_kernel<<<NBLOCKS, 512>>>(times, weights, knots, out);
}

// round 13
// speedup vs baseline: 1.0043x; 1.0043x over previous
#include <cuda_runtime.h>

// Problem constants (fixed by the reference)
#define T_TOTAL   262144
#define S_DIM     512
#define K_ROWS    258       // NUM_KNOTS + DEGREE - 1
#define NKNOTS    262       // NUM_KNOTS + 2*DEGREE
#define DEG       3

#define TIMES_PER_BLOCK 128
#define NBLOCKS (T_TOTAL / TIMES_PER_BLOCK)   // 2048

// Scratch for weight row sums (allocation-free per harness rules)
__device__ float g_rowsum[K_ROWS];

// ---------------------------------------------------------------------------
// Kernel 1: rowsum[r] = sum_s W[r, s]   (258 x 512, negligible cost)
// ---------------------------------------------------------------------------
__global__ void rowsum_kernel(const float* __restrict__ weights) {
    const int row = blockIdx.x;
    float s = 0.0f;
    for (int c = threadIdx.x; c < S_DIM; c += blockDim.x)
        s += weights[row * S_DIM + c];
    #pragma unroll
    for (int o = 16; o > 0; o >>= 1)
        s += __shfl_down_sync(0xffffffffu, s, o);
    __shared__ float ws[4];
    const int w = threadIdx.x >> 5;
    if ((threadIdx.x & 31) == 0) ws[w] = s;
    __syncthreads();
    if (threadIdx.x == 0)
        g_rowsum[row] = ws[0] + ws[1] + ws[2] + ws[3];
}

// ---------------------------------------------------------------------------
// Kernel 2: 512 threads/block, 128 times/block.
//   Phase A: stage knots in smem.
//   Phase B: threads 0..127 do independent span search + de Boor, write
//            coeffs (float4) + base to smem, per-time sum to gmem.
//   Phase C: 32 streaming iterations; weight rows register-cached and
//            reloaded only on (warp-uniform, rare) span-base change.
// NOTE: no min-blocks clamp — R10 showed that squeezing to 32 regs spills
// the weight cache to local memory (L1 84.6%, DRAM 55%) and regresses.
// ---------------------------------------------------------------------------
__global__ __launch_bounds__(512)
void bspline_kernel(const float* __restrict__ times,
                    const float* __restrict__ weights,
                    const float* __restrict__ knots,
                    float* __restrict__ out)
{
    __shared__ float  s_knots[NKNOTS];
    __shared__ float4 s_c[TIMES_PER_BLOCK];
    __shared__ int    s_base[TIMES_PER_BLOCK];

    const int tid = threadIdx.x;
    const int t0  = blockIdx.x * TIMES_PER_BLOCK;

    // Phase A: knots -> smem
    if (tid < NKNOTS) s_knots[tid] = knots[tid];
    __syncthreads();

    // Phase B: 128 parallel coefficient computations
    if (tid < TIMES_PER_BLOCK) {
        const float t = times[t0 + tid];
        float c0 = 0.f, c1 = 0.f, c2 = 0.f, c3 = 0.f, sum = 0.f;
        int base = 0;

        // Valid half-open span exists only if t < knots[258] (= t_max).
        // t == t_max => reference basis row is all zeros.
        if (t < s_knots[NKNOTS - DEG - 1]) {
            // binary search: largest i in [3, 257] with knots[i] <= t
            int lo = DEG, hi = NKNOTS - DEG - 2;   // 3 .. 257
            while (lo < hi) {
                const int mid = (lo + hi + 1) >> 1;
                if (s_knots[mid] <= t) lo = mid; else hi = mid - 1;
            }
            const int i = lo;  // knots[i] <= t < knots[i+1], non-empty span

            // Local de Boor triangle (all denominators > 0 in a valid span;
            // algebraically identical to the reference's recursion).
            float Nv[DEG + 1], left[DEG + 1], right[DEG + 1];
            Nv[0] = 1.0f;
            #pragma unroll
            for (int j = 1; j <= DEG; j++) {
                left[j]  = t - s_knots[i + 1 - j];
                right[j] = s_knots[i + j] - t;
                float saved = 0.0f;
                #pragma unroll
                for (int r = 0; r < j; r++) {
                    const float temp = Nv[r] / (right[r + 1] + left[j - r]);
                    Nv[r] = saved + right[r + 1] * temp;
                    saved = left[j - r] * temp;
                }
                Nv[j] = saved;
            }
            base = i - DEG;
            c0 = Nv[0]; c1 = Nv[1]; c2 = Nv[2]; c3 = Nv[3];
            sum = c0 * g_rowsum[base]     + c1 * g_rowsum[base + 1]
                + c2 * g_rowsum[base + 2] + c3 * g_rowsum[base + 3];
        }

        s_c[tid]    = make_float4(c0, c1, c2, c3);
        s_base[tid] = base;
        // b_splines_sum lives after the T*S b_splines block
        out[(size_t)T_TOTAL * S_DIM + (t0 + tid)] = sum;
    }
    __syncthreads();

    // Phase C: streaming combine + store with register-cached weight rows
    const int tl   = tid >> 7;    // 0..3: time sub-slot (warp-uniform)
    const int lane = tid & 127;   // column group
    const int col  = lane << 2;   // 4 columns per thread

    // Prime the weight-row register cache with the first slot's base
    int curBase = s_base[tl];
    {
        const float* wp0 = weights + (size_t)curBase * S_DIM + col;
        // (initial load done below via the same reload vars)
    }
    const float* wp = weights + (size_t)curBase * S_DIM + col;
    float4 w0 = __ldg((const float4*)(wp));
    float4 w1 = __ldg((const float4*)(wp + S_DIM));
    float4 w2 = __ldg((const float4*)(wp + 2 * S_DIM));
    float4 w3 = __ldg((const float4*)(wp + 3 * S_DIM));

    // Incremental pointers (fewer IMADs in the hot loop)
    float* out_ptr = out + (size_t)(t0 + tl) * S_DIM + col;
    const float4* c_ptr    = &s_c[tl];
    const int*    base_ptr = &s_base[tl];

    #pragma unroll 4
    for (int it = 0; it < TIMES_PER_BLOCK / 4; ++it) {
        const int base = *base_ptr;
        if (base != curBase) {                     // warp-uniform, rare
            curBase = base;
            const float* wq = weights + (size_t)base * S_DIM + col;
            w0 = __ldg((const float4*)(wq));
            w1 = __ldg((const float4*)(wq + S_DIM));
            w2 = __ldg((const float4*)(wq + 2 * S_DIM));
            w3 = __ldg((const float4*)(wq + 3 * S_DIM));
        }
        const float4 c = *c_ptr;                   // LDS.128 broadcast

        float4 o;
        o.x = c.x * w0.x + c.y * w1.x + c.z * w2.x + c.w * w3.x;
        o.y = c.x * w0.y + c.y * w1.y + c.z * w2.y + c.w * w3.y;
        o.z = c.x * w0.z + c.y * w1.z + c.z * w2.z + c.w * w3.z;
        o.w = c.x * w0.w + c.y * w1.w + c.z * w2.w + c.w * w3.w;

        // Streaming store: 512 MB with zero reuse — don't pollute L2.
        __stcs((float4*)out_ptr, o);

        out_ptr  += 4 * S_DIM;
        c_ptr    += 4;
        base_ptr += 4;
    }
}

// ---------------------------------------------------------------------------
// Launch: inputs are (times, weights, knots) per metadata order.
// Output buffer: [ b_splines (T*S floats) | b_splines_sum (T floats) ].
// ---------------------------------------------------------------------------
extern "C" void kernel_launch(void* const* d_in, const int* in_sizes, int n_in,
                              void* d_out, int out_size) {
    const float* times   = (const float*)d_in[0];
    const float* weights = (const float*)d_in[1];
    const float* knots   = (const float*)d_in[2];
    float* out = (float*)d_out;

    rowsum_kernel<<<K_ROWS, 128>>>(weights);
    bspline_kernel<<<NBLOCKS, 512>>>(times, weights, knots, out);
}